// round 3
// baseline (speedup 1.0000x reference)
#include <cuda_runtime.h>
#include <math.h>
#include <stdint.h>

// ---------------- problem constants ----------------
#define B_   2
#define S_   2048
#define H_   1024
#define NH_  16
#define HD_  64
#define T_   (B_*S_)      // 4096 tokens
#define FFN_ 4096
#define ROT_ 16

// ---------------- static scratch (no allocs allowed) ----------------
__device__ float d_xn [T_*H_];
__device__ float d_big[T_*FFN_];
__device__ float d_q  [T_*H_];
__device__ float d_k  [T_*H_];
__device__ float d_v  [T_*H_];
__device__ float d_o  [T_*H_];
__device__ float d_x1 [T_*H_];
__device__ float d_tmp[T_*H_];
// transposed val matrices (NT-ify all gemms)
__device__ float d_qvT[H_*H_];
__device__ float d_kvT[H_*H_];
__device__ float d_vvT[H_*H_];
__device__ float d_pvT[H_*H_];
__device__ float d_fvT[H_*FFN_];

// ---------------- helpers ----------------
__device__ __forceinline__ float gelu_exact(float x) {
    return 0.5f * x * (1.0f + erff(x * 0.7071067811865475f));
}

__device__ __forceinline__ uint32_t f2tf(float f) {
    uint32_t u;
    asm("cvt.rna.tf32.f32 %0, %1;" : "=r"(u) : "f"(f));
    return u;
}

__device__ __forceinline__ void mma_tf32(float* d, const uint32_t* a, const uint32_t* b) {
    asm volatile(
        "mma.sync.aligned.m16n8k8.row.col.f32.tf32.tf32.f32 "
        "{%0,%1,%2,%3}, {%4,%5,%6,%7}, {%8,%9}, {%0,%1,%2,%3};\n"
        : "+f"(d[0]), "+f"(d[1]), "+f"(d[2]), "+f"(d[3])
        : "r"(a[0]), "r"(a[1]), "r"(a[2]), "r"(a[3]), "r"(b[0]), "r"(b[1]));
}

__device__ __forceinline__ float block_reduce_sum(float v, float* sh) {
    int lane = threadIdx.x & 31, wid = threadIdx.x >> 5;
    #pragma unroll
    for (int o = 16; o > 0; o >>= 1) v += __shfl_down_sync(0xffffffffu, v, o);
    if (lane == 0) sh[wid] = v;
    __syncthreads();
    float r = (threadIdx.x < (blockDim.x >> 5)) ? sh[threadIdx.x] : 0.0f;
    if (wid == 0) {
        #pragma unroll
        for (int o = 4; o > 0; o >>= 1) r += __shfl_down_sync(0xffffffffu, r, o);
        if (lane == 0) sh[0] = r;
    }
    __syncthreads();
    r = sh[0];
    __syncthreads();
    return r;
}

// ---------------- transpose (for val matrices) ----------------
__global__ void transpose_kernel(const float* __restrict__ in, float* __restrict__ out,
                                 int R, int C) {
    __shared__ float t[32][33];
    int x  = blockIdx.x * 32 + threadIdx.x;
    int y0 = blockIdx.y * 32;
    #pragma unroll
    for (int i = threadIdx.y; i < 32; i += 8)
        t[i][threadIdx.x] = in[(size_t)(y0 + i) * C + x];
    __syncthreads();
    int xo  = blockIdx.y * 32 + threadIdx.x;
    int yo0 = blockIdx.x * 32;
    #pragma unroll
    for (int i = threadIdx.y; i < 32; i += 8)
        out[(size_t)(yo0 + i) * R + xo] = t[threadIdx.x][i];
}

// ---------------- LayerNorm ----------------
__global__ void ln_kernel(const float* __restrict__ x, const float* __restrict__ w,
                          const float* __restrict__ b, float* __restrict__ y) {
    __shared__ float sh[32];
    int row = blockIdx.x;
    int tid = threadIdx.x;
    const float4 v = *(const float4*)(x + (size_t)row * H_ + tid * 4);
    float s  = v.x + v.y + v.z + v.w;
    float sq = v.x*v.x + v.y*v.y + v.z*v.z + v.w*v.w;
    float S  = block_reduce_sum(s,  sh);
    float SQ = block_reduce_sum(sq, sh);
    float mu  = S * (1.0f / H_);
    float var = SQ * (1.0f / H_) - mu * mu;
    float inv = rsqrtf(var + 1e-5f);
    const float4 wv = *(const float4*)(w + tid * 4);
    const float4 bv = *(const float4*)(b + tid * 4);
    float4 o;
    o.x = (v.x - mu) * inv * wv.x + bv.x;
    o.y = (v.y - mu) * inv * wv.y + bv.y;
    o.z = (v.z - mu) * inv * wv.z + bv.z;
    o.w = (v.w - mu) * inv * wv.w + bv.w;
    *(float4*)(y + (size_t)row * H_ + tid * 4) = o;
}

// ---------------- TF32 tensor-core GEMM, NT only, 128x128x32 ----------------
// C[M,N] = alpha * A[M,K] @ B[N,K]^T
// smem stores pre-converted tf32 bits, pair-interleaved: within each 8-k group,
// float offset of k = 2*(k&3) + ((k>>2)&1)  ->  (k, k+4) adjacent -> LDS.64 frags.
#define KPAD 36

__global__ void __launch_bounds__(256, 2) tgemm_kernel(
    const float* __restrict__ A, const float* __restrict__ Bm, float* __restrict__ C,
    int M, int N, int K, float alpha)
{
    __shared__ uint32_t As[128 * KPAD];
    __shared__ uint32_t Bs[128 * KPAD];

    const int tid  = threadIdx.x;
    const int lane = tid & 31, wid = tid >> 5;
    const int wm = wid & 3, wn = wid >> 2;          // 4x2 warps, 32m x 64n each
    const int lr = lane >> 2, lc = lane & 3;
    const int bx = blockIdx.x, by = blockIdx.y;

    const int r_ld = tid >> 2;                      // 0..63
    const int g_ld = tid & 3;                       // k-group 0..3

    const float* Ab0 = A  + (size_t)(by * 128 + r_ld) * K + g_ld * 8;
    const float* Bb0 = Bm + (size_t)(bx * 128 + r_ld) * K + g_ld * 8;
    const size_t rstep = (size_t)64 * K;

    float4 stg[8];

    float acc[2][8][4];
    #pragma unroll
    for (int i = 0; i < 2; i++)
        #pragma unroll
        for (int j = 0; j < 8; j++)
            #pragma unroll
            for (int t = 0; t < 4; t++) acc[i][j][t] = 0.0f;

    const int iters = K >> 5;

    // prologue load
    {
        const float* a0 = Ab0;
        stg[0] = *(const float4*)(a0);
        stg[1] = *(const float4*)(a0 + 4);
        stg[2] = *(const float4*)(a0 + rstep);
        stg[3] = *(const float4*)(a0 + rstep + 4);
        const float* b0 = Bb0;
        stg[4] = *(const float4*)(b0);
        stg[5] = *(const float4*)(b0 + 4);
        stg[6] = *(const float4*)(b0 + rstep);
        stg[7] = *(const float4*)(b0 + rstep + 4);
    }

    for (int t = 0; t < iters; t++) {
        __syncthreads();
        // store staged tile (convert + pair-interleave)
        {
            uint32_t* pa0 = As + r_ld * KPAD + g_ld * 8;
            uint4 w;
            w.x = f2tf(stg[0].x); w.y = f2tf(stg[1].x); w.z = f2tf(stg[0].y); w.w = f2tf(stg[1].y);
            *(uint4*)pa0 = w;
            w.x = f2tf(stg[0].z); w.y = f2tf(stg[1].z); w.z = f2tf(stg[0].w); w.w = f2tf(stg[1].w);
            *(uint4*)(pa0 + 4) = w;
            uint32_t* pa1 = pa0 + 64 * KPAD;
            w.x = f2tf(stg[2].x); w.y = f2tf(stg[3].x); w.z = f2tf(stg[2].y); w.w = f2tf(stg[3].y);
            *(uint4*)pa1 = w;
            w.x = f2tf(stg[2].z); w.y = f2tf(stg[3].z); w.z = f2tf(stg[2].w); w.w = f2tf(stg[3].w);
            *(uint4*)(pa1 + 4) = w;
            uint32_t* pb0 = Bs + r_ld * KPAD + g_ld * 8;
            w.x = f2tf(stg[4].x); w.y = f2tf(stg[5].x); w.z = f2tf(stg[4].y); w.w = f2tf(stg[5].y);
            *(uint4*)pb0 = w;
            w.x = f2tf(stg[4].z); w.y = f2tf(stg[5].z); w.z = f2tf(stg[4].w); w.w = f2tf(stg[5].w);
            *(uint4*)(pb0 + 4) = w;
            uint32_t* pb1 = pb0 + 64 * KPAD;
            w.x = f2tf(stg[6].x); w.y = f2tf(stg[7].x); w.z = f2tf(stg[6].y); w.w = f2tf(stg[7].y);
            *(uint4*)pb1 = w;
            w.x = f2tf(stg[6].z); w.y = f2tf(stg[7].z); w.z = f2tf(stg[6].w); w.w = f2tf(stg[7].w);
            *(uint4*)(pb1 + 4) = w;
        }
        __syncthreads();

        // issue next tile's loads (latency hidden by MMA below)
        if (t + 1 < iters) {
            int k0 = (t + 1) << 5;
            const float* a0 = Ab0 + k0;
            stg[0] = *(const float4*)(a0);
            stg[1] = *(const float4*)(a0 + 4);
            stg[2] = *(const float4*)(a0 + rstep);
            stg[3] = *(const float4*)(a0 + rstep + 4);
            const float* b0 = Bb0 + k0;
            stg[4] = *(const float4*)(b0);
            stg[5] = *(const float4*)(b0 + 4);
            stg[6] = *(const float4*)(b0 + rstep);
            stg[7] = *(const float4*)(b0 + rstep + 4);
        }

        // MMA over 4 k-steps of 8
        #pragma unroll
        for (int ks = 0; ks < 4; ks++) {
            uint32_t a[2][4];
            #pragma unroll
            for (int mt = 0; mt < 2; mt++) {
                const uint32_t* ap = As + (wm * 32 + mt * 16 + lr) * KPAD + ks * 8 + lc * 2;
                uint2 p0 = *(const uint2*)ap;
                uint2 p1 = *(const uint2*)(ap + 8 * KPAD);
                a[mt][0] = p0.x; a[mt][1] = p1.x; a[mt][2] = p0.y; a[mt][3] = p1.y;
            }
            #pragma unroll
            for (int nt = 0; nt < 8; nt++) {
                const uint32_t* bp = Bs + (wn * 64 + nt * 8 + lr) * KPAD + ks * 8 + lc * 2;
                uint2 bb = *(const uint2*)bp;
                uint32_t bfr[2] = {bb.x, bb.y};
                mma_tf32(acc[0][nt], a[0], bfr);
                mma_tf32(acc[1][nt], a[1], bfr);
            }
        }
    }

    // epilogue
    #pragma unroll
    for (int mt = 0; mt < 2; mt++) {
        int r0 = by * 128 + wm * 32 + mt * 16 + lr;
        #pragma unroll
        for (int nt = 0; nt < 8; nt++) {
            int c = bx * 128 + wn * 64 + nt * 8 + 2 * lc;
            float2 lo = {acc[mt][nt][0] * alpha, acc[mt][nt][1] * alpha};
            float2 hi = {acc[mt][nt][2] * alpha, acc[mt][nt][3] * alpha};
            *(float2*)(C + (size_t)r0 * N + c)       = lo;
            *(float2*)(C + (size_t)(r0 + 8) * N + c) = hi;
        }
    }
}

// ---------------- gelu + L2-rownorm (in place) ----------------
__global__ void rownorm_kernel(float* __restrict__ a, int cols) {
    __shared__ float sh[32];
    int row = blockIdx.x;
    int tid = threadIdx.x;
    float* ar = a + (size_t)row * cols;
    float s = 0.0f;
    for (int c = tid * 4; c < cols; c += 1024) {
        float4 v = *(float4*)(ar + c);
        v.x = gelu_exact(v.x); v.y = gelu_exact(v.y);
        v.z = gelu_exact(v.z); v.w = gelu_exact(v.w);
        s += v.x*v.x + v.y*v.y + v.z*v.z + v.w*v.w;
        *(float4*)(ar + c) = v;
    }
    float tot = block_reduce_sum(s, sh);
    float sc = sqrtf((float)cols) * rsqrtf(tot);
    for (int c = tid * 4; c < cols; c += 1024) {
        float4 v = *(float4*)(ar + c);
        v.x *= sc; v.y *= sc; v.z *= sc; v.w *= sc;
        *(float4*)(ar + c) = v;
    }
}

// ---------------- RoPE ----------------
__global__ void rope_kernel(float* __restrict__ q, float* __restrict__ k) {
    int idx = blockIdx.x * blockDim.x + threadIdx.x;
    if (idx >= T_ * NH_) return;
    int h  = idx & (NH_ - 1);
    int bs = idx >> 4;
    int s  = bs & (S_ - 1);
    float* qp = q + (size_t)bs * H_ + h * HD_;
    float* kp = k + (size_t)bs * H_ + h * HD_;
    float qv[ROT_], kv[ROT_];
    #pragma unroll
    for (int i = 0; i < ROT_; i++) { qv[i] = qp[i]; kv[i] = kp[i]; }
    #pragma unroll
    for (int i = 0; i < ROT_ / 2; i++) {
        double invf = pow(10000.0, -(double)(2 * i) / (double)ROT_);
        double ang = (double)s * invf;
        float c  = (float)cos(ang);
        float sn = (float)sin(ang);
        float q0 = qv[i], q1 = qv[i + 8];
        qv[i]     = q0 * c - q1 * sn;
        qv[i + 8] = q1 * c + q0 * sn;
        float k0 = kv[i], k1 = kv[i + 8];
        kv[i]     = k0 * c - k1 * sn;
        kv[i + 8] = k1 * c + k0 * sn;
    }
    #pragma unroll
    for (int i = 0; i < ROT_; i++) { qp[i] = qv[i]; kp[i] = kv[i]; }
}

// ---------------- fused causal attention (tf32 mma, single pass) ----------------
// O = (sum_k gelu(qk/8)*V) * sqrt(S)/sqrt(sum_k gelu^2); masked entries exactly 0.
// Qs/Ks/Ss pre-converted + pair-interleaved (LDS.64 frags); Vs pre-converted plain.
#define ATPAD 68
__global__ void __launch_bounds__(128, 2) attn_kernel(
    const float* __restrict__ Q, const float* __restrict__ K,
    const float* __restrict__ V, float* __restrict__ O)
{
    extern __shared__ uint32_t sm[];
    uint32_t* Qs = sm;                     // [64][68] pair-interleaved
    uint32_t* Ks = Qs + 64 * ATPAD;        // [64][68] pair-interleaved
    uint32_t* Vs = Ks + 64 * ATPAD;        // [64][68] plain tf32 bits, tok x dim
    uint32_t* Ss = Vs + 64 * ATPAD;        // [64][68] pair-interleaved, q x tok

    const int qt  = blockIdx.x;
    const int bh  = blockIdx.y;
    const int b   = bh >> 4, h = bh & 15;
    const int tid = threadIdx.x;
    const int lane = tid & 31, w = tid >> 5;
    const int lr = lane >> 2, lc = lane & 3;
    const size_t base = (size_t)(b * S_) * H_ + h * HD_;

    // load Q tile: 64 rows x 8 k-groups, pair-interleaved
    #pragma unroll
    for (int it = 0; it < 4; it++) {
        int slot = tid + it * 128;
        int r = slot >> 3, g = slot & 7;
        const float* src = Q + base + (size_t)(qt * 64 + r) * H_ + g * 8;
        float4 f0 = *(const float4*)src;
        float4 f1 = *(const float4*)(src + 4);
        uint32_t* p = Qs + r * ATPAD + g * 8;
        uint4 u;
        u.x = f2tf(f0.x); u.y = f2tf(f1.x); u.z = f2tf(f0.y); u.w = f2tf(f1.y);
        *(uint4*)p = u;
        u.x = f2tf(f0.z); u.y = f2tf(f1.z); u.z = f2tf(f0.w); u.w = f2tf(f1.w);
        *(uint4*)(p + 4) = u;
    }

    float oacc[8][4];
    #pragma unroll
    for (int i = 0; i < 8; i++)
        #pragma unroll
        for (int j = 0; j < 4; j++) oacc[i][j] = 0.0f;
    float n2lo = 0.0f, n2hi = 0.0f;

    for (int kt = 0; kt <= qt; kt++) {
        __syncthreads();
        #pragma unroll
        for (int it = 0; it < 4; it++) {
            int slot = tid + it * 128;
            int r = slot >> 3, g = slot & 7;
            // K: pair-interleaved
            const float* srck = K + base + (size_t)(kt * 64 + r) * H_ + g * 8;
            float4 f0 = *(const float4*)srck;
            float4 f1 = *(const float4*)(srck + 4);
            uint32_t* p = Ks + r * ATPAD + g * 8;
            uint4 u;
            u.x = f2tf(f0.x); u.y = f2tf(f1.x); u.z = f2tf(f0.y); u.w = f2tf(f1.y);
            *(uint4*)p = u;
            u.x = f2tf(f0.z); u.y = f2tf(f1.z); u.z = f2tf(f0.w); u.w = f2tf(f1.w);
            *(uint4*)(p + 4) = u;
            // V: plain converted
            const float* srcv = V + base + (size_t)(kt * 64 + r) * H_ + g * 8;
            float4 v0 = *(const float4*)srcv;
            float4 v1 = *(const float4*)(srcv + 4);
            uint32_t* pv = Vs + r * ATPAD + g * 8;
            uint4 uv;
            uv.x = f2tf(v0.x); uv.y = f2tf(v0.y); uv.z = f2tf(v0.z); uv.w = f2tf(v0.w);
            *(uint4*)pv = uv;
            uv.x = f2tf(v1.x); uv.y = f2tf(v1.y); uv.z = f2tf(v1.z); uv.w = f2tf(v1.w);
            *(uint4*)(pv + 4) = uv;
        }
        __syncthreads();

        // S = Q K^T : per warp 16q x 64tok
        float sacc[8][4];
        #pragma unroll
        for (int i = 0; i < 8; i++)
            #pragma unroll
            for (int j = 0; j < 4; j++) sacc[i][j] = 0.0f;
        #pragma unroll
        for (int ks = 0; ks < 8; ks++) {
            const uint32_t* ap = Qs + (w * 16 + lr) * ATPAD + ks * 8 + lc * 2;
            uint2 p0 = *(const uint2*)ap;
            uint2 p1 = *(const uint2*)(ap + 8 * ATPAD);
            uint32_t a[4] = {p0.x, p1.x, p0.y, p1.y};
            #pragma unroll
            for (int nt = 0; nt < 8; nt++) {
                const uint32_t* bp = Ks + (nt * 8 + lr) * ATPAD + ks * 8 + lc * 2;
                uint2 bb = *(const uint2*)bp;
                uint32_t bfr[2] = {bb.x, bb.y};
                mma_tf32(sacc[nt], a, bfr);
            }
        }

        // mask + gelu + n2 + write Ss (tf32 bits, pair-interleaved)
        int q0 = qt * 64 + w * 16 + lr;
        // interleaved offsets for tok7 = 2lc and 2lc+1
        int t7a = 2 * lc, t7b = 2 * lc + 1;
        int oa = 2 * (t7a & 3) + ((t7a >> 2) & 1);
        int ob = 2 * (t7b & 3) + ((t7b >> 2) & 1);
        #pragma unroll
        for (int nt = 0; nt < 8; nt++) {
            int k0c = kt * 64 + nt * 8 + 2 * lc;
            float g0 = (k0c     <= q0)     ? gelu_exact(sacc[nt][0] * 0.125f) : 0.0f;
            float g1 = (k0c + 1 <= q0)     ? gelu_exact(sacc[nt][1] * 0.125f) : 0.0f;
            float g2 = (k0c     <= q0 + 8) ? gelu_exact(sacc[nt][2] * 0.125f) : 0.0f;
            float g3 = (k0c + 1 <= q0 + 8) ? gelu_exact(sacc[nt][3] * 0.125f) : 0.0f;
            n2lo += g0 * g0 + g1 * g1;
            n2hi += g2 * g2 + g3 * g3;
            Ss[(w * 16 + lr)     * ATPAD + nt * 8 + oa] = f2tf(g0);
            Ss[(w * 16 + lr)     * ATPAD + nt * 8 + ob] = f2tf(g1);
            Ss[(w * 16 + lr + 8) * ATPAD + nt * 8 + oa] = f2tf(g2);
            Ss[(w * 16 + lr + 8) * ATPAD + nt * 8 + ob] = f2tf(g3);
        }
        __syncwarp();   // Ss rows are warp-private

        // O += Ss @ Vs
        #pragma unroll
        for (int ks = 0; ks < 8; ks++) {
            const uint32_t* ap = Ss + (w * 16 + lr) * ATPAD + ks * 8 + lc * 2;
            uint2 p0 = *(const uint2*)ap;
            uint2 p1 = *(const uint2*)(ap + 8 * ATPAD);
            uint32_t a[4] = {p0.x, p1.x, p0.y, p1.y};
            #pragma unroll
            for (int nt = 0; nt < 8; nt++) {
                uint32_t bfr[2];
                bfr[0] = Vs[(ks * 8 + lc)     * ATPAD + nt * 8 + lr];
                bfr[1] = Vs[(ks * 8 + lc + 4) * ATPAD + nt * 8 + lr];
                mma_tf32(oacc[nt], a, bfr);
            }
        }
    }

    // reduce n2 across the 4 lanes sharing each row
    n2lo += __shfl_xor_sync(0xffffffffu, n2lo, 1);
    n2lo += __shfl_xor_sync(0xffffffffu, n2lo, 2);
    n2hi += __shfl_xor_sync(0xffffffffu, n2hi, 1);
    n2hi += __shfl_xor_sync(0xffffffffu, n2hi, 2);

    const float sqS = 45.25483399593904f;   // sqrt(2048)
    float sclo = sqS * rsqrtf(n2lo);
    float schi = sqS * rsqrtf(n2hi);

    int r0 = qt * 64 + w * 16 + lr;
    #pragma unroll
    for (int nt = 0; nt < 8; nt++) {
        int c = nt * 8 + 2 * lc;
        float2 lo = {oacc[nt][0] * sclo, oacc[nt][1] * sclo};
        float2 hi = {oacc[nt][2] * schi, oacc[nt][3] * schi};
        *(float2*)(O + base + (size_t)r0 * H_ + c)       = lo;
        *(float2*)(O + base + (size_t)(r0 + 8) * H_ + c) = hi;
    }
}

// ---------------- elementwise add ----------------
__global__ void add_kernel(const float* __restrict__ a, const float* __restrict__ b,
                           float* __restrict__ c, int n4) {
    int i = blockIdx.x * blockDim.x + threadIdx.x;
    if (i >= n4) return;
    float4 va = *(const float4*)(a + (size_t)i * 4);
    float4 vb = *(const float4*)(b + (size_t)i * 4);
    float4 o;
    o.x = va.x + vb.x; o.y = va.y + vb.y; o.z = va.z + vb.z; o.w = va.w + vb.w;
    *(float4*)(c + (size_t)i * 4) = o;
}

// ---------------- launch ----------------
extern "C" void kernel_launch(void* const* d_in, const int* in_sizes, int n_in,
                              void* d_out, int out_size) {
    const float* x        = (const float*)d_in[0];
    const float* ln1_w    = (const float*)d_in[1];
    const float* ln1_b    = (const float*)d_in[2];
    const float* ln2_w    = (const float*)d_in[3];
    const float* ln2_b    = (const float*)d_in[4];
    const float* q_key    = (const float*)d_in[5];
    const float* q_val    = (const float*)d_in[6];
    const float* k_key    = (const float*)d_in[7];
    const float* k_val    = (const float*)d_in[8];
    const float* v_key    = (const float*)d_in[9];
    const float* v_val    = (const float*)d_in[10];
    const float* proj_key = (const float*)d_in[11];
    const float* proj_val = (const float*)d_in[12];
    const float* ffn_key  = (const float*)d_in[13];
    const float* ffn_val  = (const float*)d_in[14];
    float* out = (float*)d_out;

    float *p_xn, *p_big, *p_q, *p_k, *p_v, *p_o, *p_x1, *p_tmp;
    float *p_qvT, *p_kvT, *p_vvT, *p_pvT, *p_fvT;
    cudaGetSymbolAddress((void**)&p_xn,  d_xn);
    cudaGetSymbolAddress((void**)&p_big, d_big);
    cudaGetSymbolAddress((void**)&p_q,   d_q);
    cudaGetSymbolAddress((void**)&p_k,   d_k);
    cudaGetSymbolAddress((void**)&p_v,   d_v);
    cudaGetSymbolAddress((void**)&p_o,   d_o);
    cudaGetSymbolAddress((void**)&p_x1,  d_x1);
    cudaGetSymbolAddress((void**)&p_tmp, d_tmp);
    cudaGetSymbolAddress((void**)&p_qvT, d_qvT);
    cudaGetSymbolAddress((void**)&p_kvT, d_kvT);
    cudaGetSymbolAddress((void**)&p_vvT, d_vvT);
    cudaGetSymbolAddress((void**)&p_pvT, d_pvT);
    cudaGetSymbolAddress((void**)&p_fvT, d_fvT);

    const float sqrtH = 32.0f;   // sqrt(1024)
    dim3 g_small(H_ / 128, T_ / 128);       // (8, 32)
    dim3 g_ffn1(FFN_ / 128, T_ / 128);      // (32, 32)
    dim3 tthr(32, 8);
    dim3 tgrd(H_ / 32, H_ / 32);
    dim3 tgrd_f(H_ / 32, FFN_ / 32);

    // transpose val matrices once (tiny)
    transpose_kernel<<<tgrd,   tthr>>>(q_val,    p_qvT, H_,   H_);
    transpose_kernel<<<tgrd,   tthr>>>(k_val,    p_kvT, H_,   H_);
    transpose_kernel<<<tgrd,   tthr>>>(v_val,    p_vvT, H_,   H_);
    transpose_kernel<<<tgrd,   tthr>>>(proj_val, p_pvT, H_,   H_);
    transpose_kernel<<<tgrd_f, tthr>>>(ffn_val,  p_fvT, FFN_, H_);

    // x -> xn
    ln_kernel<<<T_, 256>>>(x, ln1_w, ln1_b, p_xn);

    // q / k / v pattention (all NT now)
    tgemm_kernel<<<g_small, 256>>>(p_xn, q_key, p_big, T_, H_, H_, sqrtH);
    rownorm_kernel<<<T_, 256>>>(p_big, H_);
    tgemm_kernel<<<g_small, 256>>>(p_big, p_qvT, p_q, T_, H_, H_, 1.0f);

    tgemm_kernel<<<g_small, 256>>>(p_xn, k_key, p_big, T_, H_, H_, sqrtH);
    rownorm_kernel<<<T_, 256>>>(p_big, H_);
    tgemm_kernel<<<g_small, 256>>>(p_big, p_kvT, p_k, T_, H_, H_, 1.0f);

    tgemm_kernel<<<g_small, 256>>>(p_xn, v_key, p_big, T_, H_, H_, sqrtH);
    rownorm_kernel<<<T_, 256>>>(p_big, H_);
    tgemm_kernel<<<g_small, 256>>>(p_big, p_vvT, p_v, T_, H_, H_, 1.0f);

    // RoPE
    rope_kernel<<<(T_ * NH_) / 256, 256>>>(p_q, p_k);

    // attention
    {
        int smem = 4 * 64 * ATPAD * sizeof(float);   // ~69.6 KB
        cudaFuncSetAttribute(attn_kernel, cudaFuncAttributeMaxDynamicSharedMemorySize, smem);
        dim3 grid(S_ / 64, B_ * NH_);   // (32, 32)
        attn_kernel<<<grid, 128, smem>>>(p_q, p_k, p_v, p_o);
    }

    // proj pattention + residual
    tgemm_kernel<<<g_small, 256>>>(p_o, proj_key, p_big, T_, H_, H_, sqrtH);
    rownorm_kernel<<<T_, 256>>>(p_big, H_);
    tgemm_kernel<<<g_small, 256>>>(p_big, p_pvT, p_tmp, T_, H_, H_, 1.0f);
    add_kernel<<<(T_ * H_ / 4 + 255) / 256, 256>>>(x, p_tmp, p_x1, T_ * H_ / 4);

    // ffn pattention + residual
    ln_kernel<<<T_, 256>>>(p_x1, ln2_w, ln2_b, p_xn);
    tgemm_kernel<<<g_ffn1, 256>>>(p_xn, ffn_key, p_big, T_, FFN_, H_, sqrtH);
    rownorm_kernel<<<T_, 256>>>(p_big, FFN_);
    tgemm_kernel<<<g_small, 256>>>(p_big, p_fvT, p_tmp, T_, H_, FFN_, 1.0f);
    add_kernel<<<(T_ * H_ / 4 + 255) / 256, 256>>>(p_x1, p_tmp, out, T_ * H_ / 4);
}

// round 4
// speedup vs baseline: 1.2516x; 1.2516x over previous
#include <cuda_runtime.h>
#include <math.h>
#include <stdint.h>

// ---------------- problem constants ----------------
#define B_   2
#define S_   2048
#define H_   1024
#define NH_  16
#define HD_  64
#define T_   (B_*S_)      // 4096 tokens
#define FFN_ 4096
#define ROT_ 16

// ---------------- static scratch (no allocs allowed) ----------------
__device__ float d_xn [T_*H_];
__device__ float d_big[T_*FFN_];
__device__ float d_q  [T_*H_];
__device__ float d_k  [T_*H_];
__device__ float d_v  [T_*H_];
__device__ float d_o  [T_*H_];
__device__ float d_x1 [T_*H_];
__device__ float d_tmp[T_*H_];
// transposed+rounded val matrices, rounded key matrices
__device__ float d_qvT[H_*H_];
__device__ float d_kvT[H_*H_];
__device__ float d_vvT[H_*H_];
__device__ float d_pvT[H_*H_];
__device__ float d_fvT[H_*FFN_];
__device__ float d_qkR[H_*H_];
__device__ float d_kkR[H_*H_];
__device__ float d_vkR[H_*H_];
__device__ float d_pkR[H_*H_];
__device__ float d_fkR[FFN_*H_];

// ---------------- helpers ----------------
__device__ __forceinline__ float gelu_exact(float x) {
    return 0.5f * x * (1.0f + erff(x * 0.7071067811865475f));
}

__device__ __forceinline__ uint32_t f2tf(float f) {
    uint32_t u;
    asm("cvt.rna.tf32.f32 %0, %1;" : "=r"(u) : "f"(f));
    return u;
}
__device__ __forceinline__ float rnd_tf(float f) { return __uint_as_float(f2tf(f)); }

__device__ __forceinline__ void mma_tf32(float* d, const uint32_t* a, const uint32_t* b) {
    asm volatile(
        "mma.sync.aligned.m16n8k8.row.col.f32.tf32.tf32.f32 "
        "{%0,%1,%2,%3}, {%4,%5,%6,%7}, {%8,%9}, {%0,%1,%2,%3};\n"
        : "+f"(d[0]), "+f"(d[1]), "+f"(d[2]), "+f"(d[3])
        : "r"(a[0]), "r"(a[1]), "r"(a[2]), "r"(a[3]), "r"(b[0]), "r"(b[1]));
}

__device__ __forceinline__ void cp_async16(uint32_t smem_addr, const void* gptr) {
    asm volatile("cp.async.cg.shared.global [%0], [%1], 16;\n" :: "r"(smem_addr), "l"(gptr));
}
#define CP_COMMIT() asm volatile("cp.async.commit_group;\n" ::: "memory")
#define CP_WAIT(n)  asm volatile("cp.async.wait_group %0;\n" :: "n"(n) : "memory")

__device__ __forceinline__ float block_reduce_sum(float v, float* sh) {
    int lane = threadIdx.x & 31, wid = threadIdx.x >> 5;
    #pragma unroll
    for (int o = 16; o > 0; o >>= 1) v += __shfl_down_sync(0xffffffffu, v, o);
    if (lane == 0) sh[wid] = v;
    __syncthreads();
    float r = (threadIdx.x < (blockDim.x >> 5)) ? sh[threadIdx.x] : 0.0f;
    if (wid == 0) {
        #pragma unroll
        for (int o = 4; o > 0; o >>= 1) r += __shfl_down_sync(0xffffffffu, r, o);
        if (lane == 0) sh[0] = r;
    }
    __syncthreads();
    r = sh[0];
    __syncthreads();
    return r;
}

// ---------------- elementwise tf32 round ----------------
__global__ void round_kernel(const float* __restrict__ in, float* __restrict__ out, int n4) {
    int i = blockIdx.x * blockDim.x + threadIdx.x;
    if (i >= n4) return;
    float4 v = *(const float4*)(in + (size_t)i * 4);
    v.x = rnd_tf(v.x); v.y = rnd_tf(v.y); v.z = rnd_tf(v.z); v.w = rnd_tf(v.w);
    *(float4*)(out + (size_t)i * 4) = v;
}

// ---------------- transpose + round (for val matrices) ----------------
__global__ void transpose_kernel(const float* __restrict__ in, float* __restrict__ out,
                                 int R, int C) {
    __shared__ float t[32][33];
    int x  = blockIdx.x * 32 + threadIdx.x;
    int y0 = blockIdx.y * 32;
    #pragma unroll
    for (int i = threadIdx.y; i < 32; i += 8)
        t[i][threadIdx.x] = in[(size_t)(y0 + i) * C + x];
    __syncthreads();
    int xo  = blockIdx.y * 32 + threadIdx.x;
    int yo0 = blockIdx.x * 32;
    #pragma unroll
    for (int i = threadIdx.y; i < 32; i += 8)
        out[(size_t)(yo0 + i) * R + xo] = rnd_tf(t[threadIdx.x][i]);
}

// ---------------- LayerNorm (tf32-rounded output) ----------------
__global__ void ln_kernel(const float* __restrict__ x, const float* __restrict__ w,
                          const float* __restrict__ b, float* __restrict__ y) {
    __shared__ float sh[32];
    int row = blockIdx.x;
    int tid = threadIdx.x;
    const float4 v = *(const float4*)(x + (size_t)row * H_ + tid * 4);
    float s  = v.x + v.y + v.z + v.w;
    float sq = v.x*v.x + v.y*v.y + v.z*v.z + v.w*v.w;
    float S  = block_reduce_sum(s,  sh);
    float SQ = block_reduce_sum(sq, sh);
    float mu  = S * (1.0f / H_);
    float var = SQ * (1.0f / H_) - mu * mu;
    float inv = rsqrtf(var + 1e-5f);
    const float4 wv = *(const float4*)(w + tid * 4);
    const float4 bv = *(const float4*)(b + tid * 4);
    float4 o;
    o.x = rnd_tf((v.x - mu) * inv * wv.x + bv.x);
    o.y = rnd_tf((v.y - mu) * inv * wv.y + bv.y);
    o.z = rnd_tf((v.z - mu) * inv * wv.z + bv.z);
    o.w = rnd_tf((v.w - mu) * inv * wv.w + bv.w);
    *(float4*)(y + (size_t)row * H_ + tid * 4) = o;
}

// ---------------- TF32 tensor-core GEMM, NT, 128x128x32, cp.async 2-stage ----------------
// C[M,N] = alpha * A[M,K] @ B[N,K]^T.  A and B must be pre-rounded to tf32 in gmem.
#define KPAD 36

__global__ void __launch_bounds__(256, 2) ntgemm_kernel(
    const float* __restrict__ A, const float* __restrict__ Bm, float* __restrict__ C,
    int M, int N, int K, float alpha)
{
    extern __shared__ float sh[];
    const int ASZ = 128 * KPAD;
    float* As = sh;                 // [2][ASZ]
    float* Bs = sh + 2 * ASZ;       // [2][ASZ]

    const int bx = blockIdx.x, by = blockIdx.y;
    const int tid = threadIdx.x;
    const int lane = tid & 31, wid = tid >> 5;
    const int wm = wid & 3, wn = wid >> 2;             // 4x2 warp grid; warp tile 32m x 64n
    const int lr = lane >> 2, lc = lane & 3;

    float acc[2][8][4];
    #pragma unroll
    for (int i = 0; i < 2; i++)
        #pragma unroll
        for (int j = 0; j < 8; j++)
            #pragma unroll
            for (int t = 0; t < 4; t++) acc[i][j][t] = 0.0f;

    const int iters = K >> 5;

    auto load_tile = [&](int t, int buf) {
        int k0 = t << 5;
        #pragma unroll
        for (int it = 0; it < 4; it++) {
            int slot = tid + it * 256;
            int row = slot >> 3, k4 = slot & 7;
            const float* src = A + (size_t)(by * 128 + row) * K + k0 + k4 * 4;
            uint32_t dst = (uint32_t)__cvta_generic_to_shared(As + buf * ASZ + row * KPAD + k4 * 4);
            cp_async16(dst, src);
        }
        #pragma unroll
        for (int it = 0; it < 4; it++) {
            int slot = tid + it * 256;
            int row = slot >> 3, k4 = slot & 7;
            const float* src = Bm + (size_t)(bx * 128 + row) * K + k0 + k4 * 4;
            uint32_t dst = (uint32_t)__cvta_generic_to_shared(Bs + buf * ASZ + row * KPAD + k4 * 4);
            cp_async16(dst, src);
        }
    };

    load_tile(0, 0);
    CP_COMMIT();

    int buf = 0;
    for (int t = 0; t < iters; t++) {
        if (t + 1 < iters) {
            load_tile(t + 1, buf ^ 1);
            CP_COMMIT();
            CP_WAIT(1);
        } else {
            CP_WAIT(0);
        }
        __syncthreads();

        const float* Ab = As + buf * ASZ;
        const float* Bb = Bs + buf * ASZ;
        #pragma unroll
        for (int ks = 0; ks < 4; ks++) {
            int kb = ks * 8;
            uint32_t afr[2][4];
            #pragma unroll
            for (int mt = 0; mt < 2; mt++) {
                const float* ap = Ab + (wm * 32 + mt * 16 + lr) * KPAD + kb + lc;
                afr[mt][0] = __float_as_uint(ap[0]);
                afr[mt][1] = __float_as_uint(ap[8 * KPAD]);
                afr[mt][2] = __float_as_uint(ap[4]);
                afr[mt][3] = __float_as_uint(ap[8 * KPAD + 4]);
            }
            #pragma unroll
            for (int nt = 0; nt < 8; nt++) {
                const float* bp = Bb + (wn * 64 + nt * 8 + lr) * KPAD + kb + lc;
                uint32_t bfr[2];
                bfr[0] = __float_as_uint(bp[0]);
                bfr[1] = __float_as_uint(bp[4]);
                mma_tf32(acc[0][nt], afr[0], bfr);
                mma_tf32(acc[1][nt], afr[1], bfr);
            }
        }
        buf ^= 1;
        __syncthreads();
    }

    // epilogue
    #pragma unroll
    for (int mt = 0; mt < 2; mt++) {
        int r0 = by * 128 + wm * 32 + mt * 16 + lr;
        #pragma unroll
        for (int nt = 0; nt < 8; nt++) {
            int c = bx * 128 + wn * 64 + nt * 8 + 2 * lc;
            float2 lo = {acc[mt][nt][0] * alpha, acc[mt][nt][1] * alpha};
            float2 hi = {acc[mt][nt][2] * alpha, acc[mt][nt][3] * alpha};
            *(float2*)(C + (size_t)r0 * N + c)       = lo;
            *(float2*)(C + (size_t)(r0 + 8) * N + c) = hi;
        }
    }
}

// ---------------- gelu + L2-rownorm (in place, tf32-rounded output) ----------------
__global__ void rownorm_kernel(float* __restrict__ a, int cols) {
    __shared__ float sh[32];
    int row = blockIdx.x;
    int tid = threadIdx.x;
    float* ar = a + (size_t)row * cols;
    float s = 0.0f;
    for (int c = tid * 4; c < cols; c += 1024) {
        float4 v = *(float4*)(ar + c);
        v.x = gelu_exact(v.x); v.y = gelu_exact(v.y);
        v.z = gelu_exact(v.z); v.w = gelu_exact(v.w);
        s += v.x*v.x + v.y*v.y + v.z*v.z + v.w*v.w;
        *(float4*)(ar + c) = v;
    }
    float tot = block_reduce_sum(s, sh);
    float sc = sqrtf((float)cols) * rsqrtf(tot);
    for (int c = tid * 4; c < cols; c += 1024) {
        float4 v = *(float4*)(ar + c);
        v.x = rnd_tf(v.x * sc); v.y = rnd_tf(v.y * sc);
        v.z = rnd_tf(v.z * sc); v.w = rnd_tf(v.w * sc);
        *(float4*)(ar + c) = v;
    }
}

// ---------------- RoPE ----------------
__global__ void rope_kernel(float* __restrict__ q, float* __restrict__ k) {
    int idx = blockIdx.x * blockDim.x + threadIdx.x;
    if (idx >= T_ * NH_) return;
    int h  = idx & (NH_ - 1);
    int bs = idx >> 4;
    int s  = bs & (S_ - 1);
    float* qp = q + (size_t)bs * H_ + h * HD_;
    float* kp = k + (size_t)bs * H_ + h * HD_;
    float qv[ROT_], kv[ROT_];
    #pragma unroll
    for (int i = 0; i < ROT_; i++) { qv[i] = qp[i]; kv[i] = kp[i]; }
    #pragma unroll
    for (int i = 0; i < ROT_ / 2; i++) {
        double invf = pow(10000.0, -(double)(2 * i) / (double)ROT_);
        double ang = (double)s * invf;
        float c  = (float)cos(ang);
        float sn = (float)sin(ang);
        float q0 = qv[i], q1 = qv[i + 8];
        qv[i]     = q0 * c - q1 * sn;
        qv[i + 8] = q1 * c + q0 * sn;
        float k0 = kv[i], k1 = kv[i + 8];
        kv[i]     = k0 * c - k1 * sn;
        kv[i + 8] = k1 * c + k0 * sn;
    }
    #pragma unroll
    for (int i = 0; i < ROT_; i++) { qp[i] = qv[i]; kp[i] = kv[i]; }
}

// ---------------- fused causal attention (tf32 mma, single pass) ----------------
// O = (sum_k gelu(qk/8)*V) * sqrt(S)/sqrt(sum_k gelu^2); masked entries exactly 0.
// Qs/Ks/Ss pre-converted + pair-interleaved (LDS.64 frags); Vs pre-converted plain.
#define ATPAD 68
__global__ void __launch_bounds__(128, 2) attn_kernel(
    const float* __restrict__ Q, const float* __restrict__ K,
    const float* __restrict__ V, float* __restrict__ O)
{
    extern __shared__ uint32_t sm[];
    uint32_t* Qs = sm;                     // [64][68] pair-interleaved
    uint32_t* Ks = Qs + 64 * ATPAD;        // [64][68] pair-interleaved
    uint32_t* Vs = Ks + 64 * ATPAD;        // [64][68] plain tf32 bits, tok x dim
    uint32_t* Ss = Vs + 64 * ATPAD;        // [64][68] pair-interleaved, q x tok

    const int qt  = blockIdx.x;
    const int bh  = blockIdx.y;
    const int b   = bh >> 4, h = bh & 15;
    const int tid = threadIdx.x;
    const int lane = tid & 31, w = tid >> 5;
    const int lr = lane >> 2, lc = lane & 3;
    const size_t base = (size_t)(b * S_) * H_ + h * HD_;

    // load Q tile: 64 rows x 8 k-groups, pair-interleaved
    #pragma unroll
    for (int it = 0; it < 4; it++) {
        int slot = tid + it * 128;
        int r = slot >> 3, g = slot & 7;
        const float* src = Q + base + (size_t)(qt * 64 + r) * H_ + g * 8;
        float4 f0 = *(const float4*)src;
        float4 f1 = *(const float4*)(src + 4);
        uint32_t* p = Qs + r * ATPAD + g * 8;
        uint4 u;
        u.x = f2tf(f0.x); u.y = f2tf(f1.x); u.z = f2tf(f0.y); u.w = f2tf(f1.y);
        *(uint4*)p = u;
        u.x = f2tf(f0.z); u.y = f2tf(f1.z); u.z = f2tf(f0.w); u.w = f2tf(f1.w);
        *(uint4*)(p + 4) = u;
    }

    float oacc[8][4];
    #pragma unroll
    for (int i = 0; i < 8; i++)
        #pragma unroll
        for (int j = 0; j < 4; j++) oacc[i][j] = 0.0f;
    float n2lo = 0.0f, n2hi = 0.0f;

    for (int kt = 0; kt <= qt; kt++) {
        __syncthreads();
        #pragma unroll
        for (int it = 0; it < 4; it++) {
            int slot = tid + it * 128;
            int r = slot >> 3, g = slot & 7;
            const float* srck = K + base + (size_t)(kt * 64 + r) * H_ + g * 8;
            float4 f0 = *(const float4*)srck;
            float4 f1 = *(const float4*)(srck + 4);
            uint32_t* p = Ks + r * ATPAD + g * 8;
            uint4 u;
            u.x = f2tf(f0.x); u.y = f2tf(f1.x); u.z = f2tf(f0.y); u.w = f2tf(f1.y);
            *(uint4*)p = u;
            u.x = f2tf(f0.z); u.y = f2tf(f1.z); u.z = f2tf(f0.w); u.w = f2tf(f1.w);
            *(uint4*)(p + 4) = u;
            const float* srcv = V + base + (size_t)(kt * 64 + r) * H_ + g * 8;
            float4 v0 = *(const float4*)srcv;
            float4 v1 = *(const float4*)(srcv + 4);
            uint32_t* pv = Vs + r * ATPAD + g * 8;
            uint4 uv;
            uv.x = f2tf(v0.x); uv.y = f2tf(v0.y); uv.z = f2tf(v0.z); uv.w = f2tf(v0.w);
            *(uint4*)pv = uv;
            uv.x = f2tf(v1.x); uv.y = f2tf(v1.y); uv.z = f2tf(v1.z); uv.w = f2tf(v1.w);
            *(uint4*)(pv + 4) = uv;
        }
        __syncthreads();

        // S = Q K^T : per warp 16q x 64tok
        float sacc[8][4];
        #pragma unroll
        for (int i = 0; i < 8; i++)
            #pragma unroll
            for (int j = 0; j < 4; j++) sacc[i][j] = 0.0f;
        #pragma unroll
        for (int ks = 0; ks < 8; ks++) {
            const uint32_t* ap = Qs + (w * 16 + lr) * ATPAD + ks * 8 + lc * 2;
            uint2 p0 = *(const uint2*)ap;
            uint2 p1 = *(const uint2*)(ap + 8 * ATPAD);
            uint32_t a[4] = {p0.x, p1.x, p0.y, p1.y};
            #pragma unroll
            for (int nt = 0; nt < 8; nt++) {
                const uint32_t* bp = Ks + (nt * 8 + lr) * ATPAD + ks * 8 + lc * 2;
                uint2 bb = *(const uint2*)bp;
                uint32_t bfr[2] = {bb.x, bb.y};
                mma_tf32(sacc[nt], a, bfr);
            }
        }

        // mask + gelu + n2 + write Ss (tf32 bits, pair-interleaved)
        int q0 = qt * 64 + w * 16 + lr;
        int t7a = 2 * lc, t7b = 2 * lc + 1;
        int oa = 2 * (t7a & 3) + ((t7a >> 2) & 1);
        int ob = 2 * (t7b & 3) + ((t7b >> 2) & 1);
        #pragma unroll
        for (int nt = 0; nt < 8; nt++) {
            int k0c = kt * 64 + nt * 8 + 2 * lc;
            float g0 = (k0c     <= q0)     ? gelu_exact(sacc[nt][0] * 0.125f) : 0.0f;
            float g1 = (k0c + 1 <= q0)     ? gelu_exact(sacc[nt][1] * 0.125f) : 0.0f;
            float g2 = (k0c     <= q0 + 8) ? gelu_exact(sacc[nt][2] * 0.125f) : 0.0f;
            float g3 = (k0c + 1 <= q0 + 8) ? gelu_exact(sacc[nt][3] * 0.125f) : 0.0f;
            n2lo += g0 * g0 + g1 * g1;
            n2hi += g2 * g2 + g3 * g3;
            Ss[(w * 16 + lr)     * ATPAD + nt * 8 + oa] = f2tf(g0);
            Ss[(w * 16 + lr)     * ATPAD + nt * 8 + ob] = f2tf(g1);
            Ss[(w * 16 + lr + 8) * ATPAD + nt * 8 + oa] = f2tf(g2);
            Ss[(w * 16 + lr + 8) * ATPAD + nt * 8 + ob] = f2tf(g3);
        }
        __syncwarp();   // Ss rows are warp-private

        // O += Ss @ Vs
        #pragma unroll
        for (int ks = 0; ks < 8; ks++) {
            const uint32_t* ap = Ss + (w * 16 + lr) * ATPAD + ks * 8 + lc * 2;
            uint2 p0 = *(const uint2*)ap;
            uint2 p1 = *(const uint2*)(ap + 8 * ATPAD);
            uint32_t a[4] = {p0.x, p1.x, p0.y, p1.y};
            #pragma unroll
            for (int nt = 0; nt < 8; nt++) {
                uint32_t bfr[2];
                bfr[0] = Vs[(ks * 8 + lc)     * ATPAD + nt * 8 + lr];
                bfr[1] = Vs[(ks * 8 + lc + 4) * ATPAD + nt * 8 + lr];
                mma_tf32(oacc[nt], a, bfr);
            }
        }
    }

    n2lo += __shfl_xor_sync(0xffffffffu, n2lo, 1);
    n2lo += __shfl_xor_sync(0xffffffffu, n2lo, 2);
    n2hi += __shfl_xor_sync(0xffffffffu, n2hi, 1);
    n2hi += __shfl_xor_sync(0xffffffffu, n2hi, 2);

    const float sqS = 45.25483399593904f;   // sqrt(2048)
    float sclo = sqS * rsqrtf(n2lo);
    float schi = sqS * rsqrtf(n2hi);

    int r0 = qt * 64 + w * 16 + lr;
    #pragma unroll
    for (int nt = 0; nt < 8; nt++) {
        int c = nt * 8 + 2 * lc;
        float2 lo = {rnd_tf(oacc[nt][0] * sclo), rnd_tf(oacc[nt][1] * sclo)};
        float2 hi = {rnd_tf(oacc[nt][2] * schi), rnd_tf(oacc[nt][3] * schi)};
        *(float2*)(O + base + (size_t)r0 * H_ + c)       = lo;
        *(float2*)(O + base + (size_t)(r0 + 8) * H_ + c) = hi;
    }
}

// ---------------- elementwise add ----------------
__global__ void add_kernel(const float* __restrict__ a, const float* __restrict__ b,
                           float* __restrict__ c, int n4) {
    int i = blockIdx.x * blockDim.x + threadIdx.x;
    if (i >= n4) return;
    float4 va = *(const float4*)(a + (size_t)i * 4);
    float4 vb = *(const float4*)(b + (size_t)i * 4);
    float4 o;
    o.x = va.x + vb.x; o.y = va.y + vb.y; o.z = va.z + vb.z; o.w = va.w + vb.w;
    *(float4*)(c + (size_t)i * 4) = o;
}

// ---------------- launch ----------------
extern "C" void kernel_launch(void* const* d_in, const int* in_sizes, int n_in,
                              void* d_out, int out_size) {
    const float* x        = (const float*)d_in[0];
    const float* ln1_w    = (const float*)d_in[1];
    const float* ln1_b    = (const float*)d_in[2];
    const float* ln2_w    = (const float*)d_in[3];
    const float* ln2_b    = (const float*)d_in[4];
    const float* q_key    = (const float*)d_in[5];
    const float* q_val    = (const float*)d_in[6];
    const float* k_key    = (const float*)d_in[7];
    const float* k_val    = (const float*)d_in[8];
    const float* v_key    = (const float*)d_in[9];
    const float* v_val    = (const float*)d_in[10];
    const float* proj_key = (const float*)d_in[11];
    const float* proj_val = (const float*)d_in[12];
    const float* ffn_key  = (const float*)d_in[13];
    const float* ffn_val  = (const float*)d_in[14];
    float* out = (float*)d_out;

    float *p_xn, *p_big, *p_q, *p_k, *p_v, *p_o, *p_x1, *p_tmp;
    float *p_qvT, *p_kvT, *p_vvT, *p_pvT, *p_fvT;
    float *p_qkR, *p_kkR, *p_vkR, *p_pkR, *p_fkR;
    cudaGetSymbolAddress((void**)&p_xn,  d_xn);
    cudaGetSymbolAddress((void**)&p_big, d_big);
    cudaGetSymbolAddress((void**)&p_q,   d_q);
    cudaGetSymbolAddress((void**)&p_k,   d_k);
    cudaGetSymbolAddress((void**)&p_v,   d_v);
    cudaGetSymbolAddress((void**)&p_o,   d_o);
    cudaGetSymbolAddress((void**)&p_x1,  d_x1);
    cudaGetSymbolAddress((void**)&p_tmp, d_tmp);
    cudaGetSymbolAddress((void**)&p_qvT, d_qvT);
    cudaGetSymbolAddress((void**)&p_kvT, d_kvT);
    cudaGetSymbolAddress((void**)&p_vvT, d_vvT);
    cudaGetSymbolAddress((void**)&p_pvT, d_pvT);
    cudaGetSymbolAddress((void**)&p_fvT, d_fvT);
    cudaGetSymbolAddress((void**)&p_qkR, d_qkR);
    cudaGetSymbolAddress((void**)&p_kkR, d_kkR);
    cudaGetSymbolAddress((void**)&p_vkR, d_vkR);
    cudaGetSymbolAddress((void**)&p_pkR, d_pkR);
    cudaGetSymbolAddress((void**)&p_fkR, d_fkR);

    const float sqrtH = 32.0f;   // sqrt(1024)
    dim3 g_small(H_ / 128, T_ / 128);       // (8, 32)
    dim3 g_ffn1(FFN_ / 128, T_ / 128);      // (32, 32)
    dim3 tthr(32, 8);
    dim3 tgrd(H_ / 32, H_ / 32);
    dim3 tgrd_f(H_ / 32, FFN_ / 32);

    const int smem_g = 4 * 128 * KPAD * 4;  // 73728
    cudaFuncSetAttribute(ntgemm_kernel, cudaFuncAttributeMaxDynamicSharedMemorySize, smem_g);

    // pre-round keys, transpose+round vals (weights; small one-time cost per replay)
    const int n4_hh = H_ * H_ / 4, n4_fh = FFN_ * H_ / 4;
    round_kernel<<<(n4_hh + 255) / 256, 256>>>(q_key,    p_qkR, n4_hh);
    round_kernel<<<(n4_hh + 255) / 256, 256>>>(k_key,    p_kkR, n4_hh);
    round_kernel<<<(n4_hh + 255) / 256, 256>>>(v_key,    p_vkR, n4_hh);
    round_kernel<<<(n4_hh + 255) / 256, 256>>>(proj_key, p_pkR, n4_hh);
    round_kernel<<<(n4_fh + 255) / 256, 256>>>(ffn_key,  p_fkR, n4_fh);
    transpose_kernel<<<tgrd,   tthr>>>(q_val,    p_qvT, H_,   H_);
    transpose_kernel<<<tgrd,   tthr>>>(k_val,    p_kvT, H_,   H_);
    transpose_kernel<<<tgrd,   tthr>>>(v_val,    p_vvT, H_,   H_);
    transpose_kernel<<<tgrd,   tthr>>>(proj_val, p_pvT, H_,   H_);
    transpose_kernel<<<tgrd_f, tthr>>>(ffn_val,  p_fvT, FFN_, H_);

    // x -> xn (rounded)
    ln_kernel<<<T_, 256>>>(x, ln1_w, ln1_b, p_xn);

    // q / k / v pattention (all NT, all operands pre-rounded)
    ntgemm_kernel<<<g_small, 256, smem_g>>>(p_xn, p_qkR, p_big, T_, H_, H_, sqrtH);
    rownorm_kernel<<<T_, 256>>>(p_big, H_);
    ntgemm_kernel<<<g_small, 256, smem_g>>>(p_big, p_qvT, p_q, T_, H_, H_, 1.0f);

    ntgemm_kernel<<<g_small, 256, smem_g>>>(p_xn, p_kkR, p_big, T_, H_, H_, sqrtH);
    rownorm_kernel<<<T_, 256>>>(p_big, H_);
    ntgemm_kernel<<<g_small, 256, smem_g>>>(p_big, p_kvT, p_k, T_, H_, H_, 1.0f);

    ntgemm_kernel<<<g_small, 256, smem_g>>>(p_xn, p_vkR, p_big, T_, H_, H_, sqrtH);
    rownorm_kernel<<<T_, 256>>>(p_big, H_);
    ntgemm_kernel<<<g_small, 256, smem_g>>>(p_big, p_vvT, p_v, T_, H_, H_, 1.0f);

    // RoPE
    rope_kernel<<<(T_ * NH_) / 256, 256>>>(p_q, p_k);

    // attention
    {
        int smem = 4 * 64 * ATPAD * sizeof(float);   // ~69.6 KB
        cudaFuncSetAttribute(attn_kernel, cudaFuncAttributeMaxDynamicSharedMemorySize, smem);
        dim3 grid(S_ / 64, B_ * NH_);   // (32, 32)
        attn_kernel<<<grid, 128, smem>>>(p_q, p_k, p_v, p_o);
    }

    // proj pattention + residual
    ntgemm_kernel<<<g_small, 256, smem_g>>>(p_o, p_pkR, p_big, T_, H_, H_, sqrtH);
    rownorm_kernel<<<T_, 256>>>(p_big, H_);
    ntgemm_kernel<<<g_small, 256, smem_g>>>(p_big, p_pvT, p_tmp, T_, H_, H_, 1.0f);
    add_kernel<<<(T_ * H_ / 4 + 255) / 256, 256>>>(x, p_tmp, p_x1, T_ * H_ / 4);

    // ffn pattention + residual
    ln_kernel<<<T_, 256>>>(p_x1, ln2_w, ln2_b, p_xn);
    ntgemm_kernel<<<g_ffn1, 256, smem_g>>>(p_xn, p_fkR, p_big, T_, FFN_, H_, sqrtH);
    rownorm_kernel<<<T_, 256>>>(p_big, FFN_);
    ntgemm_kernel<<<g_small, 256, smem_g>>>(p_big, p_fvT, p_tmp, T_, H_, FFN_, 1.0f);
    add_kernel<<<(T_ * H_ / 4 + 255) / 256, 256>>>(p_x1, p_tmp, out, T_ * H_ / 4);
}